// round 9
// baseline (speedup 1.0000x reference)
#include <cuda_runtime.h>
#include <cuda_bf16.h>
#include <cstdint>

// DirGCNConv, N=100000, E=1600000, D=128, alpha=0.5.
// CSR gather aggregation (no float atomics) -> bf16-split tensor-core GEMM.
// edge_index arrives as int32.

#define MAXN  100000
#define MAXNP 100096          // 782 * 128, padded rows stay zero
#define MAXE  1600000
#define DFEAT 128
#define KTOT  256             // [fwd 0..127 | bwd 128..255]

// ---------------- static device scratch ----------------
__device__ int    g_deg_out[MAXN];
__device__ int    g_deg_in [MAXN];
__device__ int    g_rs_fwd [MAXN + 1];
__device__ int    g_rs_bwd [MAXN + 1];
__device__ int    g_cur_fwd[MAXN];
__device__ int    g_cur_bwd[MAXN];
__device__ float  g_dinv_out[MAXN];
__device__ float  g_dinv_in [MAXN];
__device__ int    g_adj_fwd[MAXE];
__device__ int    g_adj_bwd[MAXE];
// A = [aggF | aggB] as bf16 hi/lo, row-major, K contiguous (256 bf16 per row).
__device__ uint2  g_Ahi[MAXNP * 64];   // 64 uint2 = 256 bf16 per row
__device__ uint2  g_Alo[MAXNP * 64];
// W packed in mma B-fragment order: [c 0..127][kchunk 0..15][q 0..3]
// uint4 = { b0_hi, b1_hi, b0_lo, b1_lo }
__device__ uint4  g_Wpack[128 * 16 * 4];
__device__ float  g_biasC[128];

// ---------------- helpers ----------------
__device__ __forceinline__ unsigned pack2bf(float a, float b) {
    __nv_bfloat162 v = __floats2bfloat162_rn(a, b);   // x=a low, y=b high
    return *(unsigned*)&v;
}
__device__ __forceinline__ void split_hl(float f, float& h, float& l) {
    __nv_bfloat16 hb = __float2bfloat16_rn(f);
    h = __bfloat162float(hb);
    l = f - h;
}

// ---------------- K1: zero degree counters ----------------
__global__ void k_zero_deg(int n) {
    int i = blockIdx.x * blockDim.x + threadIdx.x;
    if (i < n) { g_deg_out[i] = 0; g_deg_in[i] = 0; }
}

// ---------------- K2: degree counts ----------------
__global__ void k_degree(const int* __restrict__ ei, int E) {
    int e = blockIdx.x * blockDim.x + threadIdx.x;
    if (e >= E) return;
    atomicAdd(&g_deg_out[ei[e]], 1);
    atomicAdd(&g_deg_in [ei[E + e]], 1);
}

// ---------------- K3: exclusive scan + dinv ----------------
__global__ void k_scan_dinv(int n) {
    int which = blockIdx.x;
    const int* deg  = which ? g_deg_in  : g_deg_out;
    int*       rs   = which ? g_rs_bwd  : g_rs_fwd;
    int*       cur  = which ? g_cur_bwd : g_cur_fwd;
    float*     dinv = which ? g_dinv_in : g_dinv_out;

    int t = threadIdx.x, nthr = blockDim.x;
    int chunk = (n + nthr - 1) / nthr;
    int lo = t * chunk, hi = lo + chunk;
    if (hi > n) hi = n; if (lo > n) lo = n;

    int s = 0;
    for (int j = lo; j < hi; j++) s += deg[j];

    __shared__ int wsum[32];
    int lane = t & 31, wid = t >> 5;
    int v = s;
    #pragma unroll
    for (int o = 1; o < 32; o <<= 1) {
        int u = __shfl_up_sync(0xffffffffu, v, o);
        if (lane >= o) v += u;
    }
    if (lane == 31) wsum[wid] = v;
    __syncthreads();
    if (t < 32) {
        int w = (t < (nthr >> 5)) ? wsum[t] : 0;
        #pragma unroll
        for (int o = 1; o < 32; o <<= 1) {
            int u = __shfl_up_sync(0xffffffffu, w, o);
            if (lane >= o) w += u;
        }
        wsum[t] = w;
    }
    __syncthreads();
    int run = v - s + (wid ? wsum[wid - 1] : 0);
    for (int j = lo; j < hi; j++) {
        int d = deg[j];
        rs[j] = run; cur[j] = run;
        dinv[j] = (d > 0) ? rsqrtf((float)d) : 0.f;
        run += d;
    }
    if (t == nthr - 1) rs[n] = run;
}

// ---------------- K4: fill adjacency ----------------
__global__ void k_fill(const int* __restrict__ ei, int E) {
    int e = blockIdx.x * blockDim.x + threadIdx.x;
    if (e >= E) return;
    int r = ei[e], c = ei[E + e];
    g_adj_fwd[atomicAdd(&g_cur_fwd[r], 1)] = c;
    g_adj_bwd[atomicAdd(&g_cur_bwd[c], 1)] = r;
}

// ---------------- K5: pack W + bias ----------------
__global__ void k_wpack(const float* __restrict__ Wsrc, const float* __restrict__ bsrc,
                        const float* __restrict__ Wdst, const float* __restrict__ bdst) {
    int t = blockIdx.x * blockDim.x + threadIdx.x;
    if (t >= 128 * 16 * 4) return;
    int q = t & 3, kc = (t >> 2) & 15, c = t >> 6;
    int k0 = kc * 16 + 2 * q;            // b0 pair, b1 pair at k0+8
    float f[4];
    #pragma unroll
    for (int i = 0; i < 4; i++) {
        int k = k0 + (i >> 1) * 8 + (i & 1);
        f[i] = (k < DFEAT) ? 0.5f * Wsrc[c * DFEAT + k]
                           : 0.5f * Wdst[c * DFEAT + (k - DFEAT)];
    }
    float h[4], l[4];
    #pragma unroll
    for (int i = 0; i < 4; i++) split_hl(f[i], h[i], l[i]);
    uint4 o;
    o.x = pack2bf(h[0], h[1]);   // b0 hi
    o.y = pack2bf(h[2], h[3]);   // b1 hi
    o.z = pack2bf(l[0], l[1]);   // b0 lo
    o.w = pack2bf(l[2], l[3]);   // b1 lo
    g_Wpack[t] = o;
    if (t < 128) g_biasC[t] = 0.5f * (bsrc[t] + bdst[t]);
}

// ---------------- K6: gather aggregation (warp per node) ----------------
__global__ void __launch_bounds__(256) k_aggregate(const float* __restrict__ x, int n) {
    int node = (blockIdx.x * blockDim.x + threadIdx.x) >> 5;
    int lane = threadIdx.x & 31;
    if (node >= n) return;

    const float4* x4 = (const float4*)x;
    float dio = g_dinv_out[node];
    float dii = g_dinv_in[node];

    float4 a0 = make_float4(0.f,0.f,0.f,0.f), a1 = a0, b0v = a0, b1v = a0;

    int b0 = g_rs_fwd[node], e0 = g_rs_fwd[node + 1];
    int j = b0;
    for (; j + 1 < e0; j += 2) {
        int c0 = g_adj_fwd[j], c1 = g_adj_fwd[j + 1];
        float w0 = dio * g_dinv_in[c0], w1 = dio * g_dinv_in[c1];
        float4 v0 = x4[(size_t)c0 * 32 + lane];
        float4 v1 = x4[(size_t)c1 * 32 + lane];
        a0.x += w0*v0.x; a0.y += w0*v0.y; a0.z += w0*v0.z; a0.w += w0*v0.w;
        a1.x += w1*v1.x; a1.y += w1*v1.y; a1.z += w1*v1.z; a1.w += w1*v1.w;
    }
    if (j < e0) {
        int c0 = g_adj_fwd[j];
        float w0 = dio * g_dinv_in[c0];
        float4 v0 = x4[(size_t)c0 * 32 + lane];
        a0.x += w0*v0.x; a0.y += w0*v0.y; a0.z += w0*v0.z; a0.w += w0*v0.w;
    }
    float4 aF = make_float4(a0.x+a1.x, a0.y+a1.y, a0.z+a1.z, a0.w+a1.w);

    int b1 = g_rs_bwd[node], e1 = g_rs_bwd[node + 1];
    j = b1;
    for (; j + 1 < e1; j += 2) {
        int r0 = g_adj_bwd[j], r1 = g_adj_bwd[j + 1];
        float w0 = dii * g_dinv_out[r0], w1 = dii * g_dinv_out[r1];
        float4 v0 = x4[(size_t)r0 * 32 + lane];
        float4 v1 = x4[(size_t)r1 * 32 + lane];
        b0v.x += w0*v0.x; b0v.y += w0*v0.y; b0v.z += w0*v0.z; b0v.w += w0*v0.w;
        b1v.x += w1*v1.x; b1v.y += w1*v1.y; b1v.z += w1*v1.z; b1v.w += w1*v1.w;
    }
    if (j < e1) {
        int r0 = g_adj_bwd[j];
        float w0 = dii * g_dinv_out[r0];
        float4 v0 = x4[(size_t)r0 * 32 + lane];
        b0v.x += w0*v0.x; b0v.y += w0*v0.y; b0v.z += w0*v0.z; b0v.w += w0*v0.w;
    }
    float4 aB = make_float4(b0v.x+b1v.x, b0v.y+b1v.y, b0v.z+b1v.z, b0v.w+b1v.w);

    // hi/lo split + packed stores. Lane owns k = 4*lane .. 4*lane+3.
    float fh[4], fl[4], bh[4], bl[4];
    split_hl(aF.x, fh[0], fl[0]); split_hl(aF.y, fh[1], fl[1]);
    split_hl(aF.z, fh[2], fl[2]); split_hl(aF.w, fh[3], fl[3]);
    split_hl(aB.x, bh[0], bl[0]); split_hl(aB.y, bh[1], bl[1]);
    split_hl(aB.z, bh[2], bl[2]); split_hl(aB.w, bh[3], bl[3]);

    size_t base = (size_t)node * 64 + lane;
    g_Ahi[base]      = make_uint2(pack2bf(fh[0], fh[1]), pack2bf(fh[2], fh[3]));
    g_Alo[base]      = make_uint2(pack2bf(fl[0], fl[1]), pack2bf(fl[2], fl[3]));
    g_Ahi[base + 32] = make_uint2(pack2bf(bh[0], bh[1]), pack2bf(bh[2], bh[3]));
    g_Alo[base + 32] = make_uint2(pack2bf(bl[0], bl[1]), pack2bf(bl[2], bl[3]));
}

// ---------------- K7: bf16-split tensor GEMM ----------------
// out[r][c] = sum_k A[r][k]*W'[c][k] + biasC[c], K=256, via 3x bf16 mma.
__device__ __forceinline__ void mma16816(float* c, unsigned a0, unsigned a1,
                                         unsigned a2, unsigned a3,
                                         unsigned b0, unsigned b1) {
    asm volatile(
        "mma.sync.aligned.m16n8k16.row.col.f32.bf16.bf16.f32 "
        "{%0,%1,%2,%3}, {%4,%5,%6,%7}, {%8,%9}, {%0,%1,%2,%3};\n"
        : "+f"(c[0]), "+f"(c[1]), "+f"(c[2]), "+f"(c[3])
        : "r"(a0), "r"(a1), "r"(a2), "r"(a3), "r"(b0), "r"(b1));
}

__global__ void __launch_bounds__(256) k_gemm_mma(float* __restrict__ out, int n) {
    int wid  = threadIdx.x >> 5;
    int lane = threadIdx.x & 31;
    int q    = lane & 3;
    int rowf = lane >> 2;                  // 0..7
    int r0   = blockIdx.x * 128 + wid * 16;

    const unsigned* Ah = (const unsigned*)g_Ahi;   // uint idx = row*128 + k/2
    const unsigned* Al = (const unsigned*)g_Alo;

    float acc[16][4];
    #pragma unroll
    for (int nt = 0; nt < 16; nt++)
        #pragma unroll
        for (int i = 0; i < 4; i++) acc[nt][i] = 0.f;

    #pragma unroll 1
    for (int kc = 0; kc < 16; kc++) {
        size_t ab = (size_t)(r0 + rowf) * 128 + kc * 8 + q;
        unsigned a0h = Ah[ab],            a2h = Ah[ab + 4];
        unsigned a1h = Ah[ab + 8 * 128],  a3h = Ah[ab + 8 * 128 + 4];
        unsigned a0l = Al[ab],            a2l = Al[ab + 4];
        unsigned a1l = Al[ab + 8 * 128],  a3l = Al[ab + 8 * 128 + 4];

        #pragma unroll
        for (int nt = 0; nt < 16; nt++) {
            uint4 wp = g_Wpack[(((nt * 8 + rowf) * 16) + kc) * 4 + q];
            mma16816(acc[nt], a0h, a1h, a2h, a3h, wp.x, wp.y);  // Ah*Wh
            mma16816(acc[nt], a0h, a1h, a2h, a3h, wp.z, wp.w);  // Ah*Wl
            mma16816(acc[nt], a0l, a1l, a2l, a3l, wp.x, wp.y);  // Al*Wh
        }
    }

    #pragma unroll
    for (int nt = 0; nt < 16; nt++) {
        int col = nt * 8 + q * 2;
        float2 bb = *(const float2*)&g_biasC[col];
        int r = r0 + rowf;
        if (r < n) {
            float2 v = make_float2(acc[nt][0] + bb.x, acc[nt][1] + bb.y);
            *(float2*)&out[(size_t)r * 128 + col] = v;
        }
        if (r + 8 < n) {
            float2 v = make_float2(acc[nt][2] + bb.x, acc[nt][3] + bb.y);
            *(float2*)&out[(size_t)(r + 8) * 128 + col] = v;
        }
    }
}

// ---------------- launch ----------------
extern "C" void kernel_launch(void* const* d_in, const int* in_sizes, int n_in,
                              void* d_out, int out_size) {
    const float* x    = (const float*)d_in[0];
    const int*   ei   = (const int*)d_in[1];    // int32
    const float* Wsrc = (const float*)d_in[2];
    const float* bsrc = (const float*)d_in[3];
    const float* Wdst = (const float*)d_in[4];
    const float* bdst = (const float*)d_in[5];
    float*       out  = (float*)d_out;

    int n = in_sizes[0] / DFEAT;   // 100000
    int E = in_sizes[1] / 2;       // 1600000

    k_zero_deg<<<(n + 1023) / 1024, 1024>>>(n);
    k_degree<<<(E + 255) / 256, 256>>>(ei, E);
    k_wpack<<<(128 * 16 * 4 + 255) / 256, 256>>>(Wsrc, bsrc, Wdst, bdst);
    k_scan_dinv<<<2, 1024>>>(n);
    k_fill<<<(E + 255) / 256, 256>>>(ei, E);
    k_aggregate<<<(n * 32 + 255) / 256, 256>>>(x, n);
    k_gemm_mma<<<(n + 127) / 128, 256>>>(out, n);
}

// round 10
// speedup vs baseline: 1.6848x; 1.6848x over previous
#include <cuda_runtime.h>
#include <cuda_bf16.h>
#include <cstdint>

// DirGCNConv, N=100000, E=1600000, D=128, alpha=0.5.
// CSR gather aggregation (no float atomics) -> bf16-split tensor-core GEMM.
// edge_index arrives as int32.

#define MAXN  100000
#define MAXNP 100096          // 782 * 128, padded rows stay zero
#define MAXE  1600000
#define DFEAT 128

// 3-phase scan config: 128 blocks x 256 threads x 4 items = 131072 >= MAXN
#define SCAN_B 128
#define SCAN_T 256
#define SCAN_I 4

// ---------------- static device scratch ----------------
__device__ int    g_deg_out[MAXN];
__device__ int    g_deg_in [MAXN];
__device__ int    g_rs_fwd [MAXN + 1];
__device__ int    g_rs_bwd [MAXN + 1];
__device__ int    g_cur_fwd[MAXN];
__device__ int    g_cur_bwd[MAXN];
__device__ float  g_dinv_out[MAXN];
__device__ float  g_dinv_in [MAXN];
__device__ int    g_adj_fwd[MAXE];
__device__ int    g_adj_bwd[MAXE];
__device__ int    g_bsum[2][SCAN_B];
// A = [aggF | aggB] as bf16 hi/lo, row-major, K contiguous (256 bf16 per row).
__device__ uint2  g_Ahi[MAXNP * 64];
__device__ uint2  g_Alo[MAXNP * 64];
// W packed in mma B-fragment order: [c 0..127][kchunk 0..15][q 0..3]
__device__ uint4  g_Wpack[128 * 16 * 4];
__device__ float  g_biasC[128];

// ---------------- helpers ----------------
__device__ __forceinline__ unsigned pack2bf(float a, float b) {
    __nv_bfloat162 v = __floats2bfloat162_rn(a, b);
    return *(unsigned*)&v;
}
__device__ __forceinline__ void split_hl(float f, float& h, float& l) {
    __nv_bfloat16 hb = __float2bfloat16_rn(f);
    h = __bfloat162float(hb);
    l = f - h;
}

// ---------------- K1: zero degree counters ----------------
__global__ void k_zero_deg(int n) {
    int i = blockIdx.x * blockDim.x + threadIdx.x;
    if (i < n) { g_deg_out[i] = 0; g_deg_in[i] = 0; }
}

// ---------------- K2: degree counts ----------------
__global__ void k_degree(const int* __restrict__ ei, int E) {
    int e = blockIdx.x * blockDim.x + threadIdx.x;
    if (e >= E) return;
    atomicAdd(&g_deg_out[ei[e]], 1);
    atomicAdd(&g_deg_in [ei[E + e]], 1);
}

// ---------------- K3a: per-block degree sums ----------------
__global__ void k_scan1(int n) {
    int which = blockIdx.y;
    const int* deg = which ? g_deg_in : g_deg_out;
    int blk = blockIdx.x, t = threadIdx.x;
    int base = blk * SCAN_T * SCAN_I;
    int s = 0;
    #pragma unroll
    for (int i = 0; i < SCAN_I; i++) {
        int j = base + i * SCAN_T + t;
        if (j < n) s += deg[j];
    }
    __shared__ int ws[8];
    #pragma unroll
    for (int o = 16; o; o >>= 1) s += __shfl_down_sync(0xffffffffu, s, o);
    if ((t & 31) == 0) ws[t >> 5] = s;
    __syncthreads();
    if (t < 8) {
        int v = ws[t];
        #pragma unroll
        for (int o = 4; o; o >>= 1) v += __shfl_down_sync(0xffu, v, o);
        if (t == 0) g_bsum[which][blk] = v;
    }
}

// ---------------- K3b: scan the 128 block sums ----------------
__global__ void k_scan2(int n) {
    int which = blockIdx.x;
    int t = threadIdx.x;                  // 128 threads
    int orig = g_bsum[which][t];
    int v = orig;
    __shared__ int ws[4];
    int lane = t & 31, w = t >> 5;
    #pragma unroll
    for (int o = 1; o < 32; o <<= 1) {
        int u = __shfl_up_sync(0xffffffffu, v, o);
        if (lane >= o) v += u;
    }
    if (lane == 31) ws[w] = v;
    __syncthreads();
    int add = 0;
    for (int i = 0; i < w; i++) add += ws[i];
    v += add;
    g_bsum[which][t] = v - orig;          // exclusive block offset
    if (t == 127) {
        int* rs = which ? g_rs_bwd : g_rs_fwd;
        rs[n] = v;                        // grand total
    }
}

// ---------------- K3c: per-block scan + write rs/cur/dinv ----------------
__global__ void k_scan3(int n) {
    int which = blockIdx.y;
    const int* deg  = which ? g_deg_in  : g_deg_out;
    int*       rs   = which ? g_rs_bwd  : g_rs_fwd;
    int*       cur  = which ? g_cur_bwd : g_cur_fwd;
    float*     dinv = which ? g_dinv_in : g_dinv_out;
    int blk = blockIdx.x, t = threadIdx.x;
    int base = blk * SCAN_T * SCAN_I;

    __shared__ int sdeg[SCAN_T * SCAN_I];
    __shared__ int spre[SCAN_T * SCAN_I];
    __shared__ int wsum[8];

    #pragma unroll
    for (int i = 0; i < SCAN_I; i++) {
        int j = base + i * SCAN_T + t;
        sdeg[i * SCAN_T + t] = (j < n) ? deg[j] : 0;
    }
    __syncthreads();

    int l0 = t * SCAN_I;
    int loc[SCAN_I];
    int s = 0;
    #pragma unroll
    for (int i = 0; i < SCAN_I; i++) { loc[i] = s; s += sdeg[l0 + i]; }

    int lane = t & 31, w = t >> 5;
    int v = s;
    #pragma unroll
    for (int o = 1; o < 32; o <<= 1) {
        int u = __shfl_up_sync(0xffffffffu, v, o);
        if (lane >= o) v += u;
    }
    if (lane == 31) wsum[w] = v;
    __syncthreads();
    int wadd = 0;
    for (int i = 0; i < w; i++) wadd += wsum[i];
    int texcl = v - s + wadd + g_bsum[which][blk];

    #pragma unroll
    for (int i = 0; i < SCAN_I; i++) spre[l0 + i] = texcl + loc[i];
    __syncthreads();

    #pragma unroll
    for (int i = 0; i < SCAN_I; i++) {
        int j = base + i * SCAN_T + t;
        if (j < n) {
            int p = spre[i * SCAN_T + t];
            rs[j] = p; cur[j] = p;
            int d = sdeg[i * SCAN_T + t];
            dinv[j] = (d > 0) ? rsqrtf((float)d) : 0.f;
        }
    }
}

// ---------------- K4: fill adjacency ----------------
__global__ void k_fill(const int* __restrict__ ei, int E) {
    int e = blockIdx.x * blockDim.x + threadIdx.x;
    if (e >= E) return;
    int r = ei[e], c = ei[E + e];
    g_adj_fwd[atomicAdd(&g_cur_fwd[r], 1)] = c;
    g_adj_bwd[atomicAdd(&g_cur_bwd[c], 1)] = r;
}

// ---------------- K5: pack W + bias ----------------
__global__ void k_wpack(const float* __restrict__ Wsrc, const float* __restrict__ bsrc,
                        const float* __restrict__ Wdst, const float* __restrict__ bdst) {
    int t = blockIdx.x * blockDim.x + threadIdx.x;
    if (t >= 128 * 16 * 4) return;
    int q = t & 3, kc = (t >> 2) & 15, c = t >> 6;
    int k0 = kc * 16 + 2 * q;
    float f[4];
    #pragma unroll
    for (int i = 0; i < 4; i++) {
        int k = k0 + (i >> 1) * 8 + (i & 1);
        f[i] = (k < DFEAT) ? 0.5f * Wsrc[c * DFEAT + k]
                           : 0.5f * Wdst[c * DFEAT + (k - DFEAT)];
    }
    float h[4], l[4];
    #pragma unroll
    for (int i = 0; i < 4; i++) split_hl(f[i], h[i], l[i]);
    uint4 o;
    o.x = pack2bf(h[0], h[1]);
    o.y = pack2bf(h[2], h[3]);
    o.z = pack2bf(l[0], l[1]);
    o.w = pack2bf(l[2], l[3]);
    g_Wpack[t] = o;
    if (t < 128) g_biasC[t] = 0.5f * (bsrc[t] + bdst[t]);
}

// ---------------- K6: gather aggregation (warp per node) ----------------
__global__ void __launch_bounds__(256) k_aggregate(const float* __restrict__ x, int n) {
    int node = (blockIdx.x * blockDim.x + threadIdx.x) >> 5;
    int lane = threadIdx.x & 31;
    if (node >= n) return;

    const float4* x4 = (const float4*)x;
    float dio = g_dinv_out[node];
    float dii = g_dinv_in[node];

    float4 a0 = make_float4(0.f,0.f,0.f,0.f), a1 = a0, b0v = a0, b1v = a0;

    int b0 = g_rs_fwd[node], e0 = g_rs_fwd[node + 1];
    int j = b0;
    for (; j + 1 < e0; j += 2) {
        int c0 = g_adj_fwd[j], c1 = g_adj_fwd[j + 1];
        float w0 = dio * g_dinv_in[c0], w1 = dio * g_dinv_in[c1];
        float4 v0 = x4[(size_t)c0 * 32 + lane];
        float4 v1 = x4[(size_t)c1 * 32 + lane];
        a0.x += w0*v0.x; a0.y += w0*v0.y; a0.z += w0*v0.z; a0.w += w0*v0.w;
        a1.x += w1*v1.x; a1.y += w1*v1.y; a1.z += w1*v1.z; a1.w += w1*v1.w;
    }
    if (j < e0) {
        int c0 = g_adj_fwd[j];
        float w0 = dio * g_dinv_in[c0];
        float4 v0 = x4[(size_t)c0 * 32 + lane];
        a0.x += w0*v0.x; a0.y += w0*v0.y; a0.z += w0*v0.z; a0.w += w0*v0.w;
    }
    float4 aF = make_float4(a0.x+a1.x, a0.y+a1.y, a0.z+a1.z, a0.w+a1.w);

    int b1 = g_rs_bwd[node], e1 = g_rs_bwd[node + 1];
    j = b1;
    for (; j + 1 < e1; j += 2) {
        int r0 = g_adj_bwd[j], r1 = g_adj_bwd[j + 1];
        float w0 = dii * g_dinv_out[r0], w1 = dii * g_dinv_out[r1];
        float4 v0 = x4[(size_t)r0 * 32 + lane];
        float4 v1 = x4[(size_t)r1 * 32 + lane];
        b0v.x += w0*v0.x; b0v.y += w0*v0.y; b0v.z += w0*v0.z; b0v.w += w0*v0.w;
        b1v.x += w1*v1.x; b1v.y += w1*v1.y; b1v.z += w1*v1.z; b1v.w += w1*v1.w;
    }
    if (j < e1) {
        int r0 = g_adj_bwd[j];
        float w0 = dii * g_dinv_out[r0];
        float4 v0 = x4[(size_t)r0 * 32 + lane];
        b0v.x += w0*v0.x; b0v.y += w0*v0.y; b0v.z += w0*v0.z; b0v.w += w0*v0.w;
    }
    float4 aB = make_float4(b0v.x+b1v.x, b0v.y+b1v.y, b0v.z+b1v.z, b0v.w+b1v.w);

    float fh[4], fl[4], bh[4], bl[4];
    split_hl(aF.x, fh[0], fl[0]); split_hl(aF.y, fh[1], fl[1]);
    split_hl(aF.z, fh[2], fl[2]); split_hl(aF.w, fh[3], fl[3]);
    split_hl(aB.x, bh[0], bl[0]); split_hl(aB.y, bh[1], bl[1]);
    split_hl(aB.z, bh[2], bl[2]); split_hl(aB.w, bh[3], bl[3]);

    size_t base = (size_t)node * 64 + lane;
    g_Ahi[base]      = make_uint2(pack2bf(fh[0], fh[1]), pack2bf(fh[2], fh[3]));
    g_Alo[base]      = make_uint2(pack2bf(fl[0], fl[1]), pack2bf(fl[2], fl[3]));
    g_Ahi[base + 32] = make_uint2(pack2bf(bh[0], bh[1]), pack2bf(bh[2], bh[3]));
    g_Alo[base + 32] = make_uint2(pack2bf(bl[0], bl[1]), pack2bf(bl[2], bl[3]));
}

// ---------------- K7: bf16-split tensor GEMM ----------------
__device__ __forceinline__ void mma16816(float* c, unsigned a0, unsigned a1,
                                         unsigned a2, unsigned a3,
                                         unsigned b0, unsigned b1) {
    asm volatile(
        "mma.sync.aligned.m16n8k16.row.col.f32.bf16.bf16.f32 "
        "{%0,%1,%2,%3}, {%4,%5,%6,%7}, {%8,%9}, {%0,%1,%2,%3};\n"
        : "+f"(c[0]), "+f"(c[1]), "+f"(c[2]), "+f"(c[3])
        : "r"(a0), "r"(a1), "r"(a2), "r"(a3), "r"(b0), "r"(b1));
}

__global__ void __launch_bounds__(256) k_gemm_mma(float* __restrict__ out, int n) {
    int wid  = threadIdx.x >> 5;
    int lane = threadIdx.x & 31;
    int q    = lane & 3;
    int rowf = lane >> 2;
    int r0   = blockIdx.x * 128 + wid * 16;

    const unsigned* Ah = (const unsigned*)g_Ahi;
    const unsigned* Al = (const unsigned*)g_Alo;

    float acc[16][4];
    #pragma unroll
    for (int nt = 0; nt < 16; nt++)
        #pragma unroll
        for (int i = 0; i < 4; i++) acc[nt][i] = 0.f;

    #pragma unroll 1
    for (int kc = 0; kc < 16; kc++) {
        size_t ab = (size_t)(r0 + rowf) * 128 + kc * 8 + q;
        unsigned a0h = Ah[ab],            a2h = Ah[ab + 4];
        unsigned a1h = Ah[ab + 8 * 128],  a3h = Ah[ab + 8 * 128 + 4];
        unsigned a0l = Al[ab],            a2l = Al[ab + 4];
        unsigned a1l = Al[ab + 8 * 128],  a3l = Al[ab + 8 * 128 + 4];

        #pragma unroll
        for (int nt = 0; nt < 16; nt++) {
            uint4 wp = g_Wpack[(((nt * 8 + rowf) * 16) + kc) * 4 + q];
            mma16816(acc[nt], a0h, a1h, a2h, a3h, wp.x, wp.y);
            mma16816(acc[nt], a0h, a1h, a2h, a3h, wp.z, wp.w);
            mma16816(acc[nt], a0l, a1l, a2l, a3l, wp.x, wp.y);
        }
    }

    #pragma unroll
    for (int nt = 0; nt < 16; nt++) {
        int col = nt * 8 + q * 2;
        float2 bb = *(const float2*)&g_biasC[col];
        int r = r0 + rowf;
        if (r < n) {
            float2 v = make_float2(acc[nt][0] + bb.x, acc[nt][1] + bb.y);
            *(float2*)&out[(size_t)r * 128 + col] = v;
        }
        if (r + 8 < n) {
            float2 v = make_float2(acc[nt][2] + bb.x, acc[nt][3] + bb.y);
            *(float2*)&out[(size_t)(r + 8) * 128 + col] = v;
        }
    }
}

// ---------------- launch ----------------
extern "C" void kernel_launch(void* const* d_in, const int* in_sizes, int n_in,
                              void* d_out, int out_size) {
    const float* x    = (const float*)d_in[0];
    const int*   ei   = (const int*)d_in[1];    // int32
    const float* Wsrc = (const float*)d_in[2];
    const float* bsrc = (const float*)d_in[3];
    const float* Wdst = (const float*)d_in[4];
    const float* bdst = (const float*)d_in[5];
    float*       out  = (float*)d_out;

    int n = in_sizes[0] / DFEAT;   // 100000
    int E = in_sizes[1] / 2;       // 1600000

    k_zero_deg<<<(n + 1023) / 1024, 1024>>>(n);
    k_degree<<<(E + 255) / 256, 256>>>(ei, E);
    k_wpack<<<(128 * 16 * 4 + 255) / 256, 256>>>(Wsrc, bsrc, Wdst, bdst);
    k_scan1<<<dim3(SCAN_B, 2), SCAN_T>>>(n);
    k_scan2<<<2, 128>>>(n);
    k_scan3<<<dim3(SCAN_B, 2), SCAN_T>>>(n);
    k_fill<<<(E + 255) / 256, 256>>>(ei, E);
    k_aggregate<<<(n * 32 + 255) / 256, 256>>>(x, n);
    k_gemm_mma<<<(n + 127) / 128, 256>>>(out, n);
}

// round 11
// speedup vs baseline: 1.6949x; 1.0060x over previous
#include <cuda_runtime.h>
#include <cuda_bf16.h>
#include <cuda_fp16.h>
#include <cstdint>

// DirGCNConv, N=100000, E=1600000, D=128, alpha=0.5.
// fp16-gather CSR aggregation (fp32 accum) -> bf16-split tensor-core GEMM.
// edge_index arrives as int32.

#define MAXN  100000
#define MAXNP 100096          // 782 * 128, padded rows stay zero
#define MAXE  1600000
#define DFEAT 128

#define SCAN_B 128
#define SCAN_T 256
#define SCAN_I 4

// ---------------- static device scratch ----------------
__device__ int    g_deg_out[MAXN];
__device__ int    g_deg_in [MAXN];
__device__ int    g_rs_fwd [MAXN + 1];
__device__ int    g_rs_bwd [MAXN + 1];
__device__ int    g_cur_fwd[MAXN];
__device__ int    g_cur_bwd[MAXN];
__device__ float  g_dinv_out[MAXN];
__device__ float  g_dinv_in [MAXN];
__device__ int2   g_adj_fwd[MAXE];    // {nbr, weight-bits}
__device__ int2   g_adj_bwd[MAXE];
__device__ int    g_bsum[2][SCAN_B];
__device__ uint2  g_xh[MAXN * 32];    // x as half2 pairs: row = 32 uint2 = 256B
// A = [aggF | aggB] as bf16 hi/lo, row-major, K contiguous (256 bf16 per row).
__device__ uint2  g_Ahi[MAXNP * 64];
__device__ uint2  g_Alo[MAXNP * 64];
// W packed in mma B-fragment order: [c 0..127][kchunk 0..15][q 0..3]
__device__ uint4  g_Wpack[128 * 16 * 4];
__device__ float  g_biasC[128];

// ---------------- helpers ----------------
__device__ __forceinline__ unsigned pack2bf(float a, float b) {
    __nv_bfloat162 v = __floats2bfloat162_rn(a, b);
    return *(unsigned*)&v;
}
__device__ __forceinline__ void split_hl(float f, float& h, float& l) {
    __nv_bfloat16 hb = __float2bfloat16_rn(f);
    h = __bfloat162float(hb);
    l = f - h;
}

// ---------------- K1: zero degree counters ----------------
__global__ void k_zero_deg(int n) {
    int i = blockIdx.x * blockDim.x + threadIdx.x;
    if (i < n) { g_deg_out[i] = 0; g_deg_in[i] = 0; }
}

// ---------------- K1b: x -> half2 ----------------
__global__ void k_xhalf(const float* __restrict__ x, int n32) {
    int i = blockIdx.x * blockDim.x + threadIdx.x;
    if (i >= n32) return;
    float4 v = ((const float4*)x)[i];
    __half2 h0 = __floats2half2_rn(v.x, v.y);
    __half2 h1 = __floats2half2_rn(v.z, v.w);
    g_xh[i] = make_uint2(*(unsigned*)&h0, *(unsigned*)&h1);
}

// ---------------- K2: degree counts ----------------
__global__ void k_degree(const int* __restrict__ ei, int E) {
    int e = blockIdx.x * blockDim.x + threadIdx.x;
    if (e >= E) return;
    atomicAdd(&g_deg_out[ei[e]], 1);
    atomicAdd(&g_deg_in [ei[E + e]], 1);
}

// ---------------- K3a: per-block degree sums ----------------
__global__ void k_scan1(int n) {
    int which = blockIdx.y;
    const int* deg = which ? g_deg_in : g_deg_out;
    int blk = blockIdx.x, t = threadIdx.x;
    int base = blk * SCAN_T * SCAN_I;
    int s = 0;
    #pragma unroll
    for (int i = 0; i < SCAN_I; i++) {
        int j = base + i * SCAN_T + t;
        if (j < n) s += deg[j];
    }
    __shared__ int ws[8];
    #pragma unroll
    for (int o = 16; o; o >>= 1) s += __shfl_down_sync(0xffffffffu, s, o);
    if ((t & 31) == 0) ws[t >> 5] = s;
    __syncthreads();
    if (t < 8) {
        int v = ws[t];
        #pragma unroll
        for (int o = 4; o; o >>= 1) v += __shfl_down_sync(0xffu, v, o);
        if (t == 0) g_bsum[which][blk] = v;
    }
}

// ---------------- K3b: scan the 128 block sums ----------------
__global__ void k_scan2(int n) {
    int which = blockIdx.x;
    int t = threadIdx.x;
    int orig = g_bsum[which][t];
    int v = orig;
    __shared__ int ws[4];
    int lane = t & 31, w = t >> 5;
    #pragma unroll
    for (int o = 1; o < 32; o <<= 1) {
        int u = __shfl_up_sync(0xffffffffu, v, o);
        if (lane >= o) v += u;
    }
    if (lane == 31) ws[w] = v;
    __syncthreads();
    int add = 0;
    for (int i = 0; i < w; i++) add += ws[i];
    v += add;
    g_bsum[which][t] = v - orig;
    if (t == 127) {
        int* rs = which ? g_rs_bwd : g_rs_fwd;
        rs[n] = v;
    }
}

// ---------------- K3c: per-block scan + write rs/cur/dinv ----------------
__global__ void k_scan3(int n) {
    int which = blockIdx.y;
    const int* deg  = which ? g_deg_in  : g_deg_out;
    int*       rs   = which ? g_rs_bwd  : g_rs_fwd;
    int*       cur  = which ? g_cur_bwd : g_cur_fwd;
    float*     dinv = which ? g_dinv_in : g_dinv_out;
    int blk = blockIdx.x, t = threadIdx.x;
    int base = blk * SCAN_T * SCAN_I;

    __shared__ int sdeg[SCAN_T * SCAN_I];
    __shared__ int spre[SCAN_T * SCAN_I];
    __shared__ int wsum[8];

    #pragma unroll
    for (int i = 0; i < SCAN_I; i++) {
        int j = base + i * SCAN_T + t;
        sdeg[i * SCAN_T + t] = (j < n) ? deg[j] : 0;
    }
    __syncthreads();

    int l0 = t * SCAN_I;
    int loc[SCAN_I];
    int s = 0;
    #pragma unroll
    for (int i = 0; i < SCAN_I; i++) { loc[i] = s; s += sdeg[l0 + i]; }

    int lane = t & 31, w = t >> 5;
    int v = s;
    #pragma unroll
    for (int o = 1; o < 32; o <<= 1) {
        int u = __shfl_up_sync(0xffffffffu, v, o);
        if (lane >= o) v += u;
    }
    if (lane == 31) wsum[w] = v;
    __syncthreads();
    int wadd = 0;
    for (int i = 0; i < w; i++) wadd += wsum[i];
    int texcl = v - s + wadd + g_bsum[which][blk];

    #pragma unroll
    for (int i = 0; i < SCAN_I; i++) spre[l0 + i] = texcl + loc[i];
    __syncthreads();

    #pragma unroll
    for (int i = 0; i < SCAN_I; i++) {
        int j = base + i * SCAN_T + t;
        if (j < n) {
            int p = spre[i * SCAN_T + t];
            rs[j] = p; cur[j] = p;
            int d = sdeg[i * SCAN_T + t];
            dinv[j] = (d > 0) ? rsqrtf((float)d) : 0.f;
        }
    }
}

// ---------------- K4: fill adjacency with precomputed weights ----------------
__global__ void k_fill(const int* __restrict__ ei, int E) {
    int e = blockIdx.x * blockDim.x + threadIdx.x;
    if (e >= E) return;
    int r = ei[e], c = ei[E + e];
    float w = g_dinv_out[r] * g_dinv_in[c];   // same weight both directions
    int wb = __float_as_int(w);
    g_adj_fwd[atomicAdd(&g_cur_fwd[r], 1)] = make_int2(c, wb);
    g_adj_bwd[atomicAdd(&g_cur_bwd[c], 1)] = make_int2(r, wb);
}

// ---------------- K5: pack W + bias ----------------
__global__ void k_wpack(const float* __restrict__ Wsrc, const float* __restrict__ bsrc,
                        const float* __restrict__ Wdst, const float* __restrict__ bdst) {
    int t = blockIdx.x * blockDim.x + threadIdx.x;
    if (t >= 128 * 16 * 4) return;
    int q = t & 3, kc = (t >> 2) & 15, c = t >> 6;
    int k0 = kc * 16 + 2 * q;
    float f[4];
    #pragma unroll
    for (int i = 0; i < 4; i++) {
        int k = k0 + (i >> 1) * 8 + (i & 1);
        f[i] = (k < DFEAT) ? 0.5f * Wsrc[c * DFEAT + k]
                           : 0.5f * Wdst[c * DFEAT + (k - DFEAT)];
    }
    float h[4], l[4];
    #pragma unroll
    for (int i = 0; i < 4; i++) split_hl(f[i], h[i], l[i]);
    uint4 o;
    o.x = pack2bf(h[0], h[1]);
    o.y = pack2bf(h[2], h[3]);
    o.z = pack2bf(l[0], l[1]);
    o.w = pack2bf(l[2], l[3]);
    g_Wpack[t] = o;
    if (t < 128) g_biasC[t] = 0.5f * (bsrc[t] + bdst[t]);
}

// ---------------- K6: gather aggregation (warp per node, fp16 gathers) ----------------
__device__ __forceinline__ void acc_h2(float4& a, unsigned lo, unsigned hi, float w) {
    float2 f0 = __half22float2(*(__half2*)&lo);
    float2 f1 = __half22float2(*(__half2*)&hi);
    a.x += w * f0.x; a.y += w * f0.y; a.z += w * f1.x; a.w += w * f1.y;
}

__global__ void __launch_bounds__(256) k_aggregate(int n) {
    int node = (blockIdx.x * blockDim.x + threadIdx.x) >> 5;
    int lane = threadIdx.x & 31;
    if (node >= n) return;

    float4 a0 = make_float4(0.f,0.f,0.f,0.f), a1 = a0, b0v = a0, b1v = a0;

    int b0 = g_rs_fwd[node], e0 = g_rs_fwd[node + 1];
    int j = b0;
    for (; j + 1 < e0; j += 2) {
        int2 ed0 = g_adj_fwd[j], ed1 = g_adj_fwd[j + 1];
        uint2 p0 = g_xh[(size_t)ed0.x * 32 + lane];
        uint2 p1 = g_xh[(size_t)ed1.x * 32 + lane];
        acc_h2(a0, p0.x, p0.y, __int_as_float(ed0.y));
        acc_h2(a1, p1.x, p1.y, __int_as_float(ed1.y));
    }
    if (j < e0) {
        int2 ed0 = g_adj_fwd[j];
        uint2 p0 = g_xh[(size_t)ed0.x * 32 + lane];
        acc_h2(a0, p0.x, p0.y, __int_as_float(ed0.y));
    }
    float4 aF = make_float4(a0.x+a1.x, a0.y+a1.y, a0.z+a1.z, a0.w+a1.w);

    int b1 = g_rs_bwd[node], e1 = g_rs_bwd[node + 1];
    j = b1;
    for (; j + 1 < e1; j += 2) {
        int2 ed0 = g_adj_bwd[j], ed1 = g_adj_bwd[j + 1];
        uint2 p0 = g_xh[(size_t)ed0.x * 32 + lane];
        uint2 p1 = g_xh[(size_t)ed1.x * 32 + lane];
        acc_h2(b0v, p0.x, p0.y, __int_as_float(ed0.y));
        acc_h2(b1v, p1.x, p1.y, __int_as_float(ed1.y));
    }
    if (j < e1) {
        int2 ed0 = g_adj_bwd[j];
        uint2 p0 = g_xh[(size_t)ed0.x * 32 + lane];
        acc_h2(b0v, p0.x, p0.y, __int_as_float(ed0.y));
    }
    float4 aB = make_float4(b0v.x+b1v.x, b0v.y+b1v.y, b0v.z+b1v.z, b0v.w+b1v.w);

    float fh[4], fl[4], bh[4], bl[4];
    split_hl(aF.x, fh[0], fl[0]); split_hl(aF.y, fh[1], fl[1]);
    split_hl(aF.z, fh[2], fl[2]); split_hl(aF.w, fh[3], fl[3]);
    split_hl(aB.x, bh[0], bl[0]); split_hl(aB.y, bh[1], bl[1]);
    split_hl(aB.z, bh[2], bl[2]); split_hl(aB.w, bh[3], bl[3]);

    size_t base = (size_t)node * 64 + lane;
    g_Ahi[base]      = make_uint2(pack2bf(fh[0], fh[1]), pack2bf(fh[2], fh[3]));
    g_Alo[base]      = make_uint2(pack2bf(fl[0], fl[1]), pack2bf(fl[2], fl[3]));
    g_Ahi[base + 32] = make_uint2(pack2bf(bh[0], bh[1]), pack2bf(bh[2], bh[3]));
    g_Alo[base + 32] = make_uint2(pack2bf(bl[0], bl[1]), pack2bf(bl[2], bl[3]));
}

// ---------------- K7: bf16-split tensor GEMM ----------------
__device__ __forceinline__ void mma16816(float* c, unsigned a0, unsigned a1,
                                         unsigned a2, unsigned a3,
                                         unsigned b0, unsigned b1) {
    asm volatile(
        "mma.sync.aligned.m16n8k16.row.col.f32.bf16.bf16.f32 "
        "{%0,%1,%2,%3}, {%4,%5,%6,%7}, {%8,%9}, {%0,%1,%2,%3};\n"
        : "+f"(c[0]), "+f"(c[1]), "+f"(c[2]), "+f"(c[3])
        : "r"(a0), "r"(a1), "r"(a2), "r"(a3), "r"(b0), "r"(b1));
}

__global__ void __launch_bounds__(256) k_gemm_mma(float* __restrict__ out, int n) {
    int wid  = threadIdx.x >> 5;
    int lane = threadIdx.x & 31;
    int q    = lane & 3;
    int rowf = lane >> 2;
    int r0   = blockIdx.x * 128 + wid * 16;

    const unsigned* Ah = (const unsigned*)g_Ahi;
    const unsigned* Al = (const unsigned*)g_Alo;

    float acc[16][4];
    #pragma unroll
    for (int nt = 0; nt < 16; nt++)
        #pragma unroll
        for (int i = 0; i < 4; i++) acc[nt][i] = 0.f;

    #pragma unroll 1
    for (int kc = 0; kc < 16; kc++) {
        size_t ab = (size_t)(r0 + rowf) * 128 + kc * 8 + q;
        unsigned a0h = Ah[ab],            a2h = Ah[ab + 4];
        unsigned a1h = Ah[ab + 8 * 128],  a3h = Ah[ab + 8 * 128 + 4];
        unsigned a0l = Al[ab],            a2l = Al[ab + 4];
        unsigned a1l = Al[ab + 8 * 128],  a3l = Al[ab + 8 * 128 + 4];

        #pragma unroll
        for (int nt = 0; nt < 16; nt++) {
            uint4 wp = g_Wpack[(((nt * 8 + rowf) * 16) + kc) * 4 + q];
            mma16816(acc[nt], a0h, a1h, a2h, a3h, wp.x, wp.y);
            mma16816(acc[nt], a0h, a1h, a2h, a3h, wp.z, wp.w);
            mma16816(acc[nt], a0l, a1l, a2l, a3l, wp.x, wp.y);
        }
    }

    #pragma unroll
    for (int nt = 0; nt < 16; nt++) {
        int col = nt * 8 + q * 2;
        float2 bb = *(const float2*)&g_biasC[col];
        int r = r0 + rowf;
        if (r < n) {
            float2 v = make_float2(acc[nt][0] + bb.x, acc[nt][1] + bb.y);
            *(float2*)&out[(size_t)r * 128 + col] = v;
        }
        if (r + 8 < n) {
            float2 v = make_float2(acc[nt][2] + bb.x, acc[nt][3] + bb.y);
            *(float2*)&out[(size_t)(r + 8) * 128 + col] = v;
        }
    }
}

// ---------------- launch ----------------
extern "C" void kernel_launch(void* const* d_in, const int* in_sizes, int n_in,
                              void* d_out, int out_size) {
    const float* x    = (const float*)d_in[0];
    const int*   ei   = (const int*)d_in[1];    // int32
    const float* Wsrc = (const float*)d_in[2];
    const float* bsrc = (const float*)d_in[3];
    const float* Wdst = (const float*)d_in[4];
    const float* bdst = (const float*)d_in[5];
    float*       out  = (float*)d_out;

    int n = in_sizes[0] / DFEAT;   // 100000
    int E = in_sizes[1] / 2;       // 1600000

    k_zero_deg<<<(n + 1023) / 1024, 1024>>>(n);
    k_xhalf<<<(n * 32 + 255) / 256, 256>>>(x, n * 32);
    k_degree<<<(E + 255) / 256, 256>>>(ei, E);
    k_wpack<<<(128 * 16 * 4 + 255) / 256, 256>>>(Wsrc, bsrc, Wdst, bdst);
    k_scan1<<<dim3(SCAN_B, 2), SCAN_T>>>(n);
    k_scan2<<<2, 128>>>(n);
    k_scan3<<<dim3(SCAN_B, 2), SCAN_T>>>(n);
    k_fill<<<(E + 255) / 256, 256>>>(ei, E);
    k_aggregate<<<(n * 32 + 255) / 256, 256>>>(n);
    k_gemm_mma<<<(n + 127) / 128, 256>>>(out, n);
}